// round 3
// baseline (speedup 1.0000x reference)
#include <cuda_runtime.h>

#define N_TOK   16384      // B*T = 8*2048
#define EDIM    1024
#define DHEAD   32
#define MFEAT   256

// scratch (allocation-free rule: __device__ globals)
__device__ float g_z[N_TOK * DHEAD];   // z = q+k (bias included)
__device__ float g_s[N_TOK];           // s = 0.5*(|q|^2+|k|^2)

// ---------------------------------------------------------------------------
// Kernel 1: fused q/k projection.
//   C[64 tokens x 64 cols] = x_tile[64,1024] @ [Wq | Wk][1024,64]
//   cols 0..31 = q dims, 32..63 = k dims. Epilogue forms z and s.
// BM=64, BN=64, BK=32, 128 threads, per-thread tile 8x4 (cols {2tc,2tc+1,2tc+32,2tc+33})
// ---------------------------------------------------------------------------
__global__ __launch_bounds__(128) void proj_kernel(
    const float* __restrict__ x,
    const float* __restrict__ Wq, const float* __restrict__ bq,
    const float* __restrict__ Wk, const float* __restrict__ bk)
{
    __shared__ float As[2][32][64];   // [buf][k][row]
    __shared__ float Bs[2][32][64];   // [buf][k][col]
    __shared__ float Ps[16][64];      // partial |q|^2+|k|^2 per (colgroup,row)

    const int tid  = threadIdx.x;
    const int tr   = tid & 7;         // row group: rows tr*8 .. tr*8+7
    const int tc   = tid >> 3;        // col group 0..15
    const int row0 = blockIdx.x * 64;

    float acc[8][4];
    #pragma unroll
    for (int i = 0; i < 8; i++)
        acc[i][0] = acc[i][1] = acc[i][2] = acc[i][3] = 0.f;

    const int NT = EDIM / 32;

    // preload tile 0
    #pragma unroll
    for (int i = 0; i < 4; i++) {
        int idx = i * 128 + tid;
        int xr = idx >> 3, kq = idx & 7;
        float4 v = *(const float4*)&x[(size_t)(row0 + xr) * EDIM + kq * 4];
        As[0][kq * 4 + 0][xr] = v.x; As[0][kq * 4 + 1][xr] = v.y;
        As[0][kq * 4 + 2][xr] = v.z; As[0][kq * 4 + 3][xr] = v.w;
        int k = idx >> 4, c4 = idx & 15;
        float4 wv;
        if (c4 < 8) wv = *(const float4*)&Wq[(size_t)k * 32 + c4 * 4];
        else        wv = *(const float4*)&Wk[(size_t)k * 32 + (c4 - 8) * 4];
        *(float4*)&Bs[0][k][(c4 < 8) ? c4 * 4 : 32 + (c4 - 8) * 4] = wv;
    }
    __syncthreads();

    for (int t = 0; t < NT; t++) {
        float4 xa[4], wa[4];
        if (t + 1 < NT) {
            int kt = (t + 1) * 32;
            #pragma unroll
            for (int i = 0; i < 4; i++) {
                int idx = i * 128 + tid;
                int xr = idx >> 3, kq = idx & 7;
                xa[i] = *(const float4*)&x[(size_t)(row0 + xr) * EDIM + kt + kq * 4];
                int k = idx >> 4, c4 = idx & 15;
                if (c4 < 8) wa[i] = *(const float4*)&Wq[(size_t)(kt + k) * 32 + c4 * 4];
                else        wa[i] = *(const float4*)&Wk[(size_t)(kt + k) * 32 + (c4 - 8) * 4];
            }
        }
        const int buf = t & 1;
        #pragma unroll
        for (int k = 0; k < 32; k++) {
            float4 a0 = *(const float4*)&As[buf][k][tr * 8];
            float4 a1 = *(const float4*)&As[buf][k][tr * 8 + 4];
            float2 b0 = *(const float2*)&Bs[buf][k][2 * tc];
            float2 b1 = *(const float2*)&Bs[buf][k][32 + 2 * tc];
            float a[8] = {a0.x, a0.y, a0.z, a0.w, a1.x, a1.y, a1.z, a1.w};
            #pragma unroll
            for (int i = 0; i < 8; i++) {
                acc[i][0] += a[i] * b0.x;
                acc[i][1] += a[i] * b0.y;
                acc[i][2] += a[i] * b1.x;
                acc[i][3] += a[i] * b1.y;
            }
        }
        if (t + 1 < NT) {
            const int nb = (t + 1) & 1;
            #pragma unroll
            for (int i = 0; i < 4; i++) {
                int idx = i * 128 + tid;
                int xr = idx >> 3, kq = idx & 7;
                As[nb][kq * 4 + 0][xr] = xa[i].x; As[nb][kq * 4 + 1][xr] = xa[i].y;
                As[nb][kq * 4 + 2][xr] = xa[i].z; As[nb][kq * 4 + 3][xr] = xa[i].w;
                int k = idx >> 4, c4 = idx & 15;
                *(float4*)&Bs[nb][k][(c4 < 8) ? c4 * 4 : 32 + (c4 - 8) * 4] = wa[i];
            }
        }
        __syncthreads();
    }

    // epilogue: z = q+k (with biases), partial zsqr
    const float bq0 = bq[2 * tc], bq1 = bq[2 * tc + 1];
    const float bk0 = bk[2 * tc], bk1 = bk[2 * tc + 1];
    #pragma unroll
    for (int i = 0; i < 8; i++) {
        int row = tr * 8 + i;
        int tok = row0 + row;
        float q0 = acc[i][0] + bq0, q1 = acc[i][1] + bq1;
        float k0 = acc[i][2] + bk0, k1 = acc[i][3] + bk1;
        *(float2*)&g_z[(size_t)tok * DHEAD + 2 * tc] = make_float2(q0 + k0, q1 + k1);
        Ps[tc][row] = q0 * q0 + q1 * q1 + k0 * k0 + k1 * k1;
    }
    __syncthreads();
    if (tid < 64) {
        float s = 0.f;
        #pragma unroll
        for (int j = 0; j < 16; j++) s += Ps[j][tid];
        g_s[row0 + tid] = 0.5f * s;
    }
}

// ---------------------------------------------------------------------------
// Kernel 2: R[t,m] = 0.5*(exp(u-s) + exp(-u-s)),  u = z[t]·w[m]
// 256 threads (one per m, w_m in 32 regs), 32 tokens per block via smem broadcast.
// ---------------------------------------------------------------------------
__global__ __launch_bounds__(256) void feat_kernel(
    const float* __restrict__ w, float* __restrict__ out)
{
    __shared__ float zs[32][32];
    __shared__ float ss[32];
    const int m  = threadIdx.x;
    const int t0 = blockIdx.x * 32;

    float wr[32];
    #pragma unroll
    for (int j = 0; j < 8; j++) {
        float4 v = *(const float4*)&w[(size_t)m * DHEAD + j * 4];
        wr[j * 4 + 0] = v.x; wr[j * 4 + 1] = v.y;
        wr[j * 4 + 2] = v.z; wr[j * 4 + 3] = v.w;
    }
    {
        int r = m >> 3, q = m & 7;   // 256 float4 = 32 tokens * 8 float4
        *(float4*)&zs[r][q * 4] = *(const float4*)&g_z[(size_t)(t0 + r) * DHEAD + q * 4];
        if (m < 32) ss[m] = g_s[t0 + m];
    }
    __syncthreads();

    #pragma unroll 4
    for (int tt = 0; tt < 32; tt++) {
        float u = 0.f;
        #pragma unroll
        for (int j = 0; j < 8; j++) {
            float4 zv = *(const float4*)&zs[tt][j * 4];
            u += zv.x * wr[j * 4 + 0] + zv.y * wr[j * 4 + 1]
               + zv.z * wr[j * 4 + 2] + zv.w * wr[j * 4 + 3];
        }
        float s = ss[tt];
        float r = 0.5f * (__expf(u - s) + __expf(-u - s));
        out[(size_t)(t0 + tt) * MFEAT + m] = r;
    }
}

extern "C" void kernel_launch(void* const* d_in, const int* in_sizes, int n_in,
                              void* d_out, int out_size)
{
    const float* x  = (const float*)d_in[0];
    const float* Wq = (const float*)d_in[1];
    const float* bq = (const float*)d_in[2];
    const float* Wk = (const float*)d_in[3];
    const float* bk = (const float*)d_in[4];
    // d_in[5], d_in[6] = Wv, bv: unused (reference discards v)
    const float* w  = (const float*)d_in[7];
    float* out = (float*)d_out;

    proj_kernel<<<N_TOK / 64, 128>>>(x, Wq, bq, Wk, bk);
    feat_kernel<<<N_TOK / 32, 256>>>(w, out);
}